// round 11
// baseline (speedup 1.0000x reference)
#include <cuda_runtime.h>

// 2-layer LSTM (IN=16, H=32, T=512, B=4096) + MLP head, fully fused.
// R11 = R9 layer-split warp pairs (S=8, one L0 + one L1 warp per SMSP) with
// R7's MOV-FREE data layout:
//  - Weights in smem as j-pair gate quads: ihA=(wi[2jp],wi[2jp+1],wf[2jp],
//    wf[2jp+1]), ihB=(wg...,wo...). LDS.128 lands aligned register pairs.
//  - Activations staged as scalar floats; one broadcast LDS.128 yields TWO
//    j-pairs. fma.rn.f32x2 consumes both operands directly from LDS -- the
//    pack2 MOV chain of R9/R10 (~450 instr/pair-step on the LDS critical
//    path) is gone.
//  - Accumulators split-half (lo = even j, hi = odd j); one FADD per gate at
//    the cell. Barrier protocol identical to R9 (1 named 64-thread bar/step).

#define FULLMASK 0xffffffffu
typedef unsigned long long u64;

constexpr int T_LEN = 512;
constexpr int IN_DIM = 16;
constexpr int H_DIM = 32;
constexpr int SEQ_PER_PAIR = 8;
constexpr int PAIRS_PER_BLOCK = 4;
constexpr int THREADS = 256;          // warps 0-3 = L0 of pair w, 4-7 = L1

// Weight arrays: [jp][unit] float4.
//  A = (wi[2jp], wi[2jp+1], wf[2jp], wf[2jp+1])
//  B = (wg[2jp], wg[2jp+1], wo[2jp], wo[2jp+1])
struct SmemW {
    float4 ihA0[IN_DIM / 2][H_DIM];
    float4 ihB0[IN_DIM / 2][H_DIM];
    float4 hhA0[H_DIM / 2][H_DIM];
    float4 hhB0[H_DIM / 2][H_DIM];
    float4 ihA1[H_DIM / 2][H_DIM];
    float4 ihB1[H_DIM / 2][H_DIM];
    float4 hhA1[H_DIM / 2][H_DIM];
    float4 hhB1[H_DIM / 2][H_DIM];
    float4 bg0[H_DIM];   // (bi,bf,bg,bo) per unit (bih+bhh)
    float4 bg1[H_DIM];
};

// Per-pair staging, scalar floats [buf][seq][unit/dim].
struct __align__(16) Stage {
    float h0[2][SEQ_PER_PAIR][H_DIM];   // written by L0, read by both
    float h1[2][SEQ_PER_PAIR][H_DIM];   // L1-private
    float x[2][SEQ_PER_PAIR][IN_DIM];   // L0-private
};

struct SmemAll {
    SmemW w;
    Stage st[PAIRS_PER_BLOCK];
};

__device__ __forceinline__ u64 fma2(u64 a, u64 b, u64 c) {
    u64 d;
    asm("fma.rn.f32x2 %0, %1, %2, %3;" : "=l"(d) : "l"(a), "l"(b), "l"(c));
    return d;
}
__device__ __forceinline__ u64 pack2f(float a, float b) {
    u64 r;
    asm("mov.b64 %0, {%1, %2};" : "=l"(r) : "f"(a), "f"(b));
    return r;
}
__device__ __forceinline__ float2 unpack2(u64 v) {
    float2 r;
    asm("mov.b64 {%0, %1}, %2;" : "=f"(r.x), "=f"(r.y) : "l"(v));
    return r;
}
__device__ __forceinline__ float hsum2(u64 v) {
    float2 r = unpack2(v);
    return r.x + r.y;
}

__device__ __forceinline__ float fast_sigmoid(float x) {
    return __fdividef(1.0f, 1.0f + __expf(-x));
}
__device__ __forceinline__ float fast_tanh(float x) {
    float a = fabsf(x);
    float e = __expf(-2.0f * a);
    float r = __fdividef(1.0f - e, 1.0f + e);
    return copysignf(r, x);
}

__device__ __forceinline__ void pair_bar(int pair) {
    asm volatile("bar.sync %0, %1;" :: "r"(pair + 1), "r"(64) : "memory");
}

// One 2-jp group: 4 weight LDS.128 + per-seq 1 broadcast act LDS.128 + 8 fma2.
// WA/WB: weight arrays; ACTP(ss): pointer to 16B of acts [4g..4g+4) for seq ss.
#define GRP(WA, WB, g, ACTP, FIRST)                                          \
    do {                                                                     \
        ulonglong2 wA0 = *reinterpret_cast<const ulonglong2*>(&WA[2*(g)][lane]);   \
        ulonglong2 wB0 = *reinterpret_cast<const ulonglong2*>(&WB[2*(g)][lane]);   \
        ulonglong2 wA1 = *reinterpret_cast<const ulonglong2*>(&WA[2*(g)+1][lane]); \
        ulonglong2 wB1 = *reinterpret_cast<const ulonglong2*>(&WB[2*(g)+1][lane]); \
        _Pragma("unroll")                                                    \
        for (int ss = 0; ss < 8; ss++) {                                     \
            ulonglong2 a = *reinterpret_cast<const ulonglong2*>(ACTP(ss));   \
            if (FIRST) {                                                     \
                ai[ss] = fma2(wA0.x, a.x, BI);                               \
                af[ss] = fma2(wA0.y, a.x, BF);                               \
                ag[ss] = fma2(wB0.x, a.x, BG);                               \
                ao[ss] = fma2(wB0.y, a.x, BO);                               \
            } else {                                                         \
                ai[ss] = fma2(wA0.x, a.x, ai[ss]);                           \
                af[ss] = fma2(wA0.y, a.x, af[ss]);                           \
                ag[ss] = fma2(wB0.x, a.x, ag[ss]);                           \
                ao[ss] = fma2(wB0.y, a.x, ao[ss]);                           \
            }                                                                \
            ai[ss] = fma2(wA1.x, a.y, ai[ss]);                               \
            af[ss] = fma2(wA1.y, a.y, af[ss]);                               \
            ag[ss] = fma2(wB1.x, a.y, ag[ss]);                               \
            ao[ss] = fma2(wB1.y, a.y, ao[ss]);                               \
        }                                                                    \
    } while (0)

__global__ void __launch_bounds__(THREADS, 1)
lstm_fused_kernel(const float* __restrict__ x,
                  const float* __restrict__ Wih0, const float* __restrict__ Whh0,
                  const float* __restrict__ bih0, const float* __restrict__ bhh0,
                  const float* __restrict__ Wih1, const float* __restrict__ Whh1,
                  const float* __restrict__ bih1, const float* __restrict__ bhh1,
                  const float* __restrict__ W1, const float* __restrict__ b1,
                  const float* __restrict__ W2, const float* __restrict__ b2,
                  float* __restrict__ out, int batch) {
    extern __shared__ char smem_raw[];
    SmemAll* sm = reinterpret_cast<SmemAll*>(smem_raw);
    SmemW* s = &sm->w;

    const int tid = threadIdx.x;

    // ---- Stage weights as j-pair gate quads ----
    for (int i = tid; i < (IN_DIM / 2) * H_DIM; i += THREADS) {
        int jp = i / H_DIM, u = i % H_DIM;
        int j0 = 2 * jp, j1 = 2 * jp + 1;
        s->ihA0[jp][u] = make_float4(Wih0[(0 * H_DIM + u) * IN_DIM + j0],
                                     Wih0[(0 * H_DIM + u) * IN_DIM + j1],
                                     Wih0[(1 * H_DIM + u) * IN_DIM + j0],
                                     Wih0[(1 * H_DIM + u) * IN_DIM + j1]);
        s->ihB0[jp][u] = make_float4(Wih0[(2 * H_DIM + u) * IN_DIM + j0],
                                     Wih0[(2 * H_DIM + u) * IN_DIM + j1],
                                     Wih0[(3 * H_DIM + u) * IN_DIM + j0],
                                     Wih0[(3 * H_DIM + u) * IN_DIM + j1]);
    }
    for (int i = tid; i < (H_DIM / 2) * H_DIM; i += THREADS) {
        int jp = i / H_DIM, u = i % H_DIM;
        int j0 = 2 * jp, j1 = 2 * jp + 1;
        s->hhA0[jp][u] = make_float4(Whh0[(0 * H_DIM + u) * H_DIM + j0],
                                     Whh0[(0 * H_DIM + u) * H_DIM + j1],
                                     Whh0[(1 * H_DIM + u) * H_DIM + j0],
                                     Whh0[(1 * H_DIM + u) * H_DIM + j1]);
        s->hhB0[jp][u] = make_float4(Whh0[(2 * H_DIM + u) * H_DIM + j0],
                                     Whh0[(2 * H_DIM + u) * H_DIM + j1],
                                     Whh0[(3 * H_DIM + u) * H_DIM + j0],
                                     Whh0[(3 * H_DIM + u) * H_DIM + j1]);
        s->ihA1[jp][u] = make_float4(Wih1[(0 * H_DIM + u) * H_DIM + j0],
                                     Wih1[(0 * H_DIM + u) * H_DIM + j1],
                                     Wih1[(1 * H_DIM + u) * H_DIM + j0],
                                     Wih1[(1 * H_DIM + u) * H_DIM + j1]);
        s->ihB1[jp][u] = make_float4(Wih1[(2 * H_DIM + u) * H_DIM + j0],
                                     Wih1[(2 * H_DIM + u) * H_DIM + j1],
                                     Wih1[(3 * H_DIM + u) * H_DIM + j0],
                                     Wih1[(3 * H_DIM + u) * H_DIM + j1]);
        s->hhA1[jp][u] = make_float4(Whh1[(0 * H_DIM + u) * H_DIM + j0],
                                     Whh1[(0 * H_DIM + u) * H_DIM + j1],
                                     Whh1[(1 * H_DIM + u) * H_DIM + j0],
                                     Whh1[(1 * H_DIM + u) * H_DIM + j1]);
        s->hhB1[jp][u] = make_float4(Whh1[(2 * H_DIM + u) * H_DIM + j0],
                                     Whh1[(2 * H_DIM + u) * H_DIM + j1],
                                     Whh1[(3 * H_DIM + u) * H_DIM + j0],
                                     Whh1[(3 * H_DIM + u) * H_DIM + j1]);
    }
    for (int u = tid; u < H_DIM; u += THREADS) {
        s->bg0[u] = make_float4(bih0[0 * H_DIM + u] + bhh0[0 * H_DIM + u],
                                bih0[1 * H_DIM + u] + bhh0[1 * H_DIM + u],
                                bih0[2 * H_DIM + u] + bhh0[2 * H_DIM + u],
                                bih0[3 * H_DIM + u] + bhh0[3 * H_DIM + u]);
        s->bg1[u] = make_float4(bih1[0 * H_DIM + u] + bhh1[0 * H_DIM + u],
                                bih1[1 * H_DIM + u] + bhh1[1 * H_DIM + u],
                                bih1[2 * H_DIM + u] + bhh1[2 * H_DIM + u],
                                bih1[3 * H_DIM + u] + bhh1[3 * H_DIM + u]);
    }

    const int warp = tid >> 5;
    const int lane = tid & 31;         // lane = hidden unit
    const int pair = warp & 3;
    const int role = warp >> 2;        // 0 = layer-0 warp, 1 = layer-1 warp
    Stage* st = &sm->st[pair];
    const int seq_base = (blockIdx.x * PAIRS_PER_BLOCK + pair) * SEQ_PER_PAIR;

    const int xs = lane >> 2;          // seq this lane loads x for
    const int xq = lane & 3;           // dim quarter
    const size_t seq_stride = (size_t)T_LEN * IN_DIM;
    const float* xload = x + (size_t)(seq_base + xs) * seq_stride + 4 * xq;

    // ---- Init staging ----
    if (seq_base < batch) {
        if (role == 0) {
#pragma unroll
            for (int ss = 0; ss < 8; ss++) st->h0[0][ss][lane] = 0.f;
            *reinterpret_cast<float4*>(&st->x[0][xs][4 * xq]) =
                *reinterpret_cast<const float4*>(xload);
        } else {
#pragma unroll
            for (int ss = 0; ss < 8; ss++) st->h1[0][ss][lane] = 0.f;
        }
    }
    __syncthreads();
    if (seq_base >= batch) return;

    if (role == 0) {
        // ================= Layer-0 warp =================
        const float4 bv = s->bg0[lane];
        const u64 BI = pack2f(bv.x, 0.f), BF = pack2f(bv.y, 0.f);
        const u64 BG = pack2f(bv.z, 0.f), BO = pack2f(bv.w, 0.f);
        float c0[8] = {0, 0, 0, 0, 0, 0, 0, 0};

        for (int t = 0; t < T_LEN; t++) {
            const int buf = t & 1, nbuf = buf ^ 1;
            float4 xn = make_float4(0.f, 0.f, 0.f, 0.f);
            if (t + 1 < T_LEN)
                xn = *reinterpret_cast<const float4*>(xload + (t + 1) * IN_DIM);

            u64 ai[8], af[8], ag[8], ao[8];
#pragma unroll
            for (int g = 0; g < IN_DIM / 4; g++) {
#define ACT_X(ss) (&st->x[buf][ss][4 * g])
                GRP(s->ihA0, s->ihB0, g, ACT_X, (g == 0));
#undef ACT_X
            }
#pragma unroll
            for (int g = 0; g < H_DIM / 4; g++) {
#define ACT_H0(ss) (&st->h0[buf][ss][4 * g])
                GRP(s->hhA0, s->hhB0, g, ACT_H0, false);
#undef ACT_H0
            }
            // Cell 0 + stage h0(t)
#pragma unroll
            for (int ss = 0; ss < 8; ss++) {
                float ig = fast_sigmoid(hsum2(ai[ss]));
                float fg = fast_sigmoid(hsum2(af[ss]));
                float gg = fast_tanh(hsum2(ag[ss]));
                float og = fast_sigmoid(hsum2(ao[ss]));
                c0[ss] = fmaf(fg, c0[ss], ig * gg);
                st->h0[nbuf][ss][lane] = og * fast_tanh(c0[ss]);
            }
            // Stage x(t+1) (L0-private buffer)
            *reinterpret_cast<float4*>(&st->x[nbuf][xs][4 * xq]) = xn;
            pair_bar(pair);  // h0(t) visible to the L1 warp
        }
        return;
    }

    // ================= Layer-1 warp =================
    const float4 bv = s->bg1[lane];
    const u64 BI = pack2f(bv.x, 0.f), BF = pack2f(bv.y, 0.f);
    const u64 BG = pack2f(bv.z, 0.f), BO = pack2f(bv.w, 0.f);
    float c1[8] = {0, 0, 0, 0, 0, 0, 0, 0};
    float h1n[8] = {0, 0, 0, 0, 0, 0, 0, 0};

    for (int t = 0; t < T_LEN; t++) {
        const int buf = t & 1, nbuf = buf ^ 1;

        u64 ai[8], af[8], ag[8], ao[8];
        // hh1 first: own h1(t-1); independent of L0's h0(t).
#pragma unroll
        for (int g = 0; g < H_DIM / 4; g++) {
#define ACT_H1(ss) (&st->h1[buf][ss][4 * g])
            GRP(s->hhA1, s->hhB1, g, ACT_H1, (g == 0));
#undef ACT_H1
        }
        pair_bar(pair);  // wait for L0's h0(t) in h0[nbuf]
#pragma unroll
        for (int g = 0; g < H_DIM / 4; g++) {
#define ACT_H0N(ss) (&st->h0[nbuf][ss][4 * g])
            GRP(s->ihA1, s->ihB1, g, ACT_H0N, false);
#undef ACT_H0N
        }
        // Cell 1 + stage h1(t)
#pragma unroll
        for (int ss = 0; ss < 8; ss++) {
            float ig = fast_sigmoid(hsum2(ai[ss]));
            float fg = fast_sigmoid(hsum2(af[ss]));
            float gg = fast_tanh(hsum2(ag[ss]));
            float og = fast_sigmoid(hsum2(ao[ss]));
            c1[ss] = fmaf(fg, c1[ss], ig * gg);
            h1n[ss] = og * fast_tanh(c1[ss]);
            st->h1[nbuf][ss][lane] = h1n[ss];
        }
        __syncwarp();  // order h1 stores vs next step's cross-lane reads
    }

    // ---- Head (L1 warp): z = relu(h1 @ W1.T + b1); y = z @ W2.T + b2 ----
    float bias2 = __ldg(b2);
    float bm = (lane < 16) ? __ldg(b1 + lane) : 0.f;
    float w2m = (lane < 16) ? __ldg(W2 + lane) : 0.f;
    float z[8];
#pragma unroll
    for (int ss = 0; ss < 8; ss++) z[ss] = bm;
#pragma unroll
    for (int j = 0; j < H_DIM; j++) {
        float wm = (lane < 16) ? __ldg(W1 + lane * H_DIM + j) : 0.f;
#pragma unroll
        for (int ss = 0; ss < 8; ss++) {
            float hj = __shfl_sync(FULLMASK, h1n[ss], j);
            z[ss] = fmaf(wm, hj, z[ss]);
        }
    }
#pragma unroll
    for (int ss = 0; ss < 8; ss++) {
        float v = fmaxf(z[ss], 0.f) * w2m;
#pragma unroll
        for (int off = 8; off >= 1; off >>= 1)
            v += __shfl_xor_sync(FULLMASK, v, off, 16);
        if (lane == 0) out[seq_base + ss] = v + bias2;
    }
}

extern "C" void kernel_launch(void* const* d_in, const int* in_sizes, int n_in,
                              void* d_out, int out_size) {
    const float* x    = (const float*)d_in[0];
    const float* Wih0 = (const float*)d_in[1];
    const float* Whh0 = (const float*)d_in[2];
    const float* bih0 = (const float*)d_in[3];
    const float* bhh0 = (const float*)d_in[4];
    const float* Wih1 = (const float*)d_in[5];
    const float* Whh1 = (const float*)d_in[6];
    const float* bih1 = (const float*)d_in[7];
    const float* bhh1 = (const float*)d_in[8];
    const float* W1   = (const float*)d_in[9];
    const float* b1   = (const float*)d_in[10];
    const float* W2   = (const float*)d_in[11];
    const float* b2   = (const float*)d_in[12];
    float* out = (float*)d_out;

    int batch = in_sizes[0] / (T_LEN * IN_DIM);  // 4096

    cudaFuncSetAttribute(lstm_fused_kernel,
                         cudaFuncAttributeMaxDynamicSharedMemorySize,
                         (int)sizeof(SmemAll));

    int pairs = (batch + SEQ_PER_PAIR - 1) / SEQ_PER_PAIR;          // 512
    int blocks = (pairs + PAIRS_PER_BLOCK - 1) / PAIRS_PER_BLOCK;   // 128
    lstm_fused_kernel<<<blocks, THREADS, sizeof(SmemAll)>>>(
        x, Wih0, Whh0, bih0, bhh0, Wih1, Whh1, bih1, bhh1,
        W1, b1, W2, b2, out, batch);
}